// round 13
// baseline (speedup 1.0000x reference)
#include <cuda_runtime.h>

#define BB 2
#define LL 512
#define DD 256
#define NN 256
#define DT 64
#define PW 576   // DT + 2*DD

// scratch (device globals — no allocations allowed); padded for the scan's
// over-prefetch past the end (values loaded but never used).
__device__ float  g_projA[(BB * LL + 16) * PW];  // split-K partial (k 0..127)
__device__ float  g_projB[(BB * LL + 16) * PW];  // split-K partial (k 128..255)
__device__ float4 g_ddx [(BB * LL + 16) * DD];   // {dt, dt*x, exp(-dt), 0} per (row, d)
__device__ float2 g_bg2 [(BB * LL + 16) * NN];   // {beta_n, gamma_n} per (row, n)

__device__ __forceinline__ float ex2_approx(float x) {
    float r;
    asm("ex2.approx.ftz.f32 %0, %1;" : "=f"(r) : "f"(x));
    return r;
}

// ---------------------------------------------------------------------------
// Kernel 1: proj = x @ W_in, split-K: blockIdx.z in {0,1} selects K half.
// 64x64 tiles over K=128 (4 chunks of 32), double-buffered smem, 256 threads,
// 4x4 micro-tile, register-pipelined LDS. grid 9x16x2 = 288 CTAs = 2/SM.
// ---------------------------------------------------------------------------
__global__ void __launch_bounds__(256) proj_kernel(const float* __restrict__ x,
                                                   const float* __restrict__ W) {
    __shared__ float xs[2][32][68];
    __shared__ float ws[2][32][64];
    const int bm = blockIdx.y * 64;
    const int bn = blockIdx.x * 64;
    const int kbase = blockIdx.z * 128;
    const int tid = threadIdx.x;
    const int tx = tid & 15;
    const int ty = tid >> 4;

    const int xr = tid >> 2;
    const int xc = (tid & 3) * 8;
    const int wr = tid >> 3;
    const int wc = (tid & 7) * 8;

    float acc[4][4] = {};

    {
        float4 a0 = *(const float4*)&x[(size_t)(bm + xr) * DD + kbase + xc];
        float4 a1 = *(const float4*)&x[(size_t)(bm + xr) * DD + kbase + xc + 4];
        xs[0][xc + 0][xr] = a0.x; xs[0][xc + 1][xr] = a0.y;
        xs[0][xc + 2][xr] = a0.z; xs[0][xc + 3][xr] = a0.w;
        xs[0][xc + 4][xr] = a1.x; xs[0][xc + 5][xr] = a1.y;
        xs[0][xc + 6][xr] = a1.z; xs[0][xc + 7][xr] = a1.w;
        *(float4*)&ws[0][wr][wc]     = *(const float4*)&W[(size_t)(kbase + wr) * PW + bn + wc];
        *(float4*)&ws[0][wr][wc + 4] = *(const float4*)&W[(size_t)(kbase + wr) * PW + bn + wc + 4];
    }
    __syncthreads();

#pragma unroll
    for (int ch = 0; ch < 4; ch++) {
        const int cur = ch & 1;
        const int nxt = cur ^ 1;
        const int k1 = kbase + (ch + 1) * 32;

        float4 a0, a1, w0, w1;
        if (ch < 3) {
            a0 = *(const float4*)&x[(size_t)(bm + xr) * DD + k1 + xc];
            a1 = *(const float4*)&x[(size_t)(bm + xr) * DD + k1 + xc + 4];
            w0 = *(const float4*)&W[(size_t)(k1 + wr) * PW + bn + wc];
            w1 = *(const float4*)&W[(size_t)(k1 + wr) * PW + bn + wc + 4];
        }

        float4 av0 = *(const float4*)&xs[cur][0][ty * 4];
        float4 bv0 = *(const float4*)&ws[cur][0][tx * 4];
#pragma unroll
        for (int k = 0; k < 32; k++) {
            float4 av1, bv1;
            if (k < 31) {
                av1 = *(const float4*)&xs[cur][k + 1][ty * 4];
                bv1 = *(const float4*)&ws[cur][k + 1][tx * 4];
            }
            float a_[4] = {av0.x, av0.y, av0.z, av0.w};
            float b_[4] = {bv0.x, bv0.y, bv0.z, bv0.w};
#pragma unroll
            for (int i = 0; i < 4; i++)
#pragma unroll
                for (int j = 0; j < 4; j++)
                    acc[i][j] = fmaf(a_[i], b_[j], acc[i][j]);
            av0 = av1; bv0 = bv1;
        }

        if (ch < 3) {
            xs[nxt][xc + 0][xr] = a0.x; xs[nxt][xc + 1][xr] = a0.y;
            xs[nxt][xc + 2][xr] = a0.z; xs[nxt][xc + 3][xr] = a0.w;
            xs[nxt][xc + 4][xr] = a1.x; xs[nxt][xc + 5][xr] = a1.y;
            xs[nxt][xc + 6][xr] = a1.z; xs[nxt][xc + 7][xr] = a1.w;
            *(float4*)&ws[nxt][wr][wc]     = w0;
            *(float4*)&ws[nxt][wr][wc + 4] = w1;
            __syncthreads();
        }
    }

    float* dst = (blockIdx.z == 0) ? g_projA : g_projB;
#pragma unroll
    for (int i = 0; i < 4; i++) {
        float4 v = make_float4(acc[i][0], acc[i][1], acc[i][2], acc[i][3]);
        *(float4*)&dst[(size_t)(bm + ty * 4 + i) * PW + bn + tx * 4] = v;
    }
}

// ---------------------------------------------------------------------------
// Kernel 2 (fused): sums the two split-K partials on the fly.
// dt = softplus(dt_raw @ W_dt + b_dt); pack {dt, dt*x, exp(-dt)};
// out = x*delta; pack {beta, gamma} per n.
// ---------------------------------------------------------------------------
__global__ void dt_kernel(const float* __restrict__ x, const float* __restrict__ Wdt,
                          const float* __restrict__ bdt, const float* __restrict__ delta,
                          float* __restrict__ out) {
    int r = blockIdx.x;
    int t = threadIdx.x;
    __shared__ float sp[DT];
    if (t < DT) sp[t] = g_projA[r * PW + t] + g_projB[r * PW + t];
    __syncthreads();
    float acc = bdt[t];
#pragma unroll
    for (int k = 0; k < DT; k++)
        acc = fmaf(sp[k], Wdt[k * DD + t], acc);
    float dt = fmaxf(acc, 0.f) + log1pf(__expf(-fabsf(acc)));
    float xv = x[r * DD + t];
    int idx = r * DD + t;
    g_ddx[idx] = make_float4(dt, dt * xv, __expf(-dt), 0.f);
    out[idx]   = xv * delta[t];
    float be = g_projA[r * PW + DT + t]      + g_projB[r * PW + DT + t];
    float ga = g_projA[r * PW + DT + DD + t] + g_projB[r * PW + DT + DD + t];
    g_bg2[(size_t)r * NN + t] = make_float2(be, ga);
}

// ---------------------------------------------------------------------------
// Kernel 3: sequential scan.
// ONE CTA per (b, d) (512 CTAs, 128 threads); each lane owns 2 n.
// dd {dt, dtx, r} preloaded to smem once per CTA. bg via one LDG.128 per
// lane per step. MUFU halved: a1 = a0 * r (alpha ladder: alpha_{n+1}=alpha_n-1).
// ---------------------------------------------------------------------------

#define LOAD_BATCH(BUF, LB) do {                                              \
    _Pragma("unroll")                                                         \
    for (int k_ = 0; k_ < 8; k_++) {                                          \
        bg[BUF][k_] = bgp[(size_t)((LB) + k_) * (NN / 2)];                    \
        dd[BUF][k_] = sdd[(LB) + k_];                                         \
    }                                                                         \
} while (0)

#define TREDUCE8(YL, VOUT) do {                                               \
    float s_, r0_, r1_, r2_, r3_, q0_, q1_;                                   \
    s_  = bt0 ? YL[0] : YL[1];                                                \
    r0_ = (bt0 ? YL[1] : YL[0]) + __shfl_xor_sync(fm, s_, 1);                 \
    s_  = bt0 ? YL[2] : YL[3];                                                \
    r1_ = (bt0 ? YL[3] : YL[2]) + __shfl_xor_sync(fm, s_, 1);                 \
    s_  = bt0 ? YL[4] : YL[5];                                                \
    r2_ = (bt0 ? YL[5] : YL[4]) + __shfl_xor_sync(fm, s_, 1);                 \
    s_  = bt0 ? YL[6] : YL[7];                                                \
    r3_ = (bt0 ? YL[7] : YL[6]) + __shfl_xor_sync(fm, s_, 1);                 \
    s_  = bt1 ? r0_ : r1_;                                                    \
    q0_ = (bt1 ? r1_ : r0_) + __shfl_xor_sync(fm, s_, 2);                     \
    s_  = bt1 ? r2_ : r3_;                                                    \
    q1_ = (bt1 ? r3_ : r2_) + __shfl_xor_sync(fm, s_, 2);                     \
    s_  = bt2 ? q0_ : q1_;                                                    \
    VOUT = (bt2 ? q1_ : q0_) + __shfl_xor_sync(fm, s_, 4);                    \
    VOUT += __shfl_xor_sync(fm, VOUT, 8);                                     \
    VOUT += __shfl_xor_sync(fm, VOUT, 16);                                    \
} while (0)

#define COMPUTE_BATCH(BUF, LB) do {                                           \
    float yl_[8];                                                             \
    _Pragma("unroll")                                                         \
    for (int k_ = 0; k_ < 8; k_++) {                                          \
        float dt_  = dd[BUF][k_].x;                                           \
        float dtx_ = dd[BUF][k_].y;                                           \
        float r_   = dd[BUF][k_].z;                                           \
        float a0_ = ex2_approx(dt_ * a2v0);                                   \
        float a1_ = a0_ * r_;                                                 \
        st0 = fmaf(a0_, st0, dtx_ * bg[BUF][k_].x);                           \
        st1 = fmaf(a1_, st1, dtx_ * bg[BUF][k_].z);                           \
        yl_[k_] = fmaf(st0, bg[BUF][k_].y, st1 * bg[BUF][k_].w);              \
    }                                                                         \
    float v_;                                                                 \
    TREDUCE8(yl_, v_);                                                        \
    if (lane < 8) ypart[warp * LL + (LB) + lane] = v_;                        \
} while (0)

__global__ void __launch_bounds__(128, 4) scan_kernel(float* __restrict__ out,
                                                      const float* __restrict__ alog) {
    __shared__ float4 sdd[LL + 16];
    __shared__ float  ypart[4 * LL];

    const int warp = threadIdx.x >> 5;
    const int lane = threadIdx.x & 31;
    const int bd = blockIdx.x;
    const int b = bd >> 8;
    const int d = bd & 255;
    const int p = warp * 32 + lane;   // n-pair index: n = 2p, 2p+1

    for (int i = threadIdx.x; i < LL; i += 128)
        sdd[i] = g_ddx[(size_t)(b * LL + i) * DD + d];
    __syncthreads();

    const float L2E = 1.4426950408889634f;
    float a2v0 = -__expf(alog[d * NN + 2 * p]) * L2E;
    float st0 = 0.f, st1 = 0.f;

    const float4* bgp = (const float4*)(g_bg2 + (size_t)(b * LL) * NN) + p;
    float* outp = out + (size_t)b * LL * DD + d;

    const unsigned fm = 0xffffffffu;
    const int bt0 = lane & 1;
    const int bt1 = (lane >> 1) & 1;
    const int bt2 = (lane >> 2) & 1;

    float4 bg[2][8];
    float4 dd[2][8];

    LOAD_BATCH(0, 0);

#pragma unroll 1
    for (int lb = 0; lb < LL; lb += 16) {
        LOAD_BATCH(1, lb + 8);
        COMPUTE_BATCH(0, lb);
        LOAD_BATCH(0, lb + 16);    // over-prefetch lands in padding (unused)
        COMPUTE_BATCH(1, lb + 8);
    }

    __syncthreads();

#pragma unroll
    for (int i = 0; i < 4; i++) {
        int l = threadIdx.x + i * 128;
        float y = ypart[l] + ypart[LL + l] + ypart[2 * LL + l] + ypart[3 * LL + l];
        outp[l * DD] += y;
    }
}

// ---------------------------------------------------------------------------
extern "C" void kernel_launch(void* const* d_in, const int* in_sizes, int n_in,
                              void* d_out, int out_size) {
    const float* x      = (const float*)d_in[0];  // [2,512,256]
    const float* W_in   = (const float*)d_in[1];  // [256,576]
    const float* W_dt   = (const float*)d_in[2];  // [64,256]
    const float* b_dt   = (const float*)d_in[3];  // [256]
    const float* alog   = (const float*)d_in[4];  // [256,256]
    const float* delta  = (const float*)d_in[5];  // [256]
    float* out = (float*)d_out;                   // [2,512,256]

    dim3 pgrid(PW / 64, (BB * LL) / 64, 2);       // (9, 16, 2) = 288 CTAs
    proj_kernel<<<pgrid, 256>>>(x, W_in);

    dt_kernel<<<BB * LL, 256>>>(x, W_dt, b_dt, delta, out);

    scan_kernel<<<BB * DD, 128>>>(out, alog);
}

// round 14
// speedup vs baseline: 1.0628x; 1.0628x over previous
#include <cuda_runtime.h>

#define BB 2
#define LL 512
#define DD 256
#define NN 256
#define DT 64
#define PW 576   // DT + 2*DD

// scratch (device globals — no allocations allowed); padded for the scan's
// over-prefetch past the end (values loaded but never used).
__device__ float  g_projA[(BB * LL + 16) * PW];  // split-K partial (k 0..127)
__device__ float  g_projB[(BB * LL + 16) * PW];  // split-K partial (k 128..255)
__device__ float2 g_ddx [(BB * LL + 16) * DD];   // {dt, dt*x} per (row, d)
__device__ float2 g_bg2 [(BB * LL + 16) * NN];   // {beta_n, gamma_n} per (row, n)

__device__ __forceinline__ float ex2_approx(float x) {
    float r;
    asm("ex2.approx.ftz.f32 %0, %1;" : "=f"(r) : "f"(x));
    return r;
}

// ---------------------------------------------------------------------------
// Kernel 1: proj = x @ W_in, split-K: blockIdx.z in {0,1} selects K half.
// 64x64 tiles over K=128 (4 chunks of 32), double-buffered smem, 256 threads,
// 4x4 micro-tile, register-pipelined LDS. grid 9x16x2 = 288 CTAs = 2/SM.
// (R13 version — measured 13.6us.)
// ---------------------------------------------------------------------------
__global__ void __launch_bounds__(256) proj_kernel(const float* __restrict__ x,
                                                   const float* __restrict__ W) {
    __shared__ float xs[2][32][68];
    __shared__ float ws[2][32][64];
    const int bm = blockIdx.y * 64;
    const int bn = blockIdx.x * 64;
    const int kbase = blockIdx.z * 128;
    const int tid = threadIdx.x;
    const int tx = tid & 15;
    const int ty = tid >> 4;

    const int xr = tid >> 2;
    const int xc = (tid & 3) * 8;
    const int wr = tid >> 3;
    const int wc = (tid & 7) * 8;

    float acc[4][4] = {};

    {
        float4 a0 = *(const float4*)&x[(size_t)(bm + xr) * DD + kbase + xc];
        float4 a1 = *(const float4*)&x[(size_t)(bm + xr) * DD + kbase + xc + 4];
        xs[0][xc + 0][xr] = a0.x; xs[0][xc + 1][xr] = a0.y;
        xs[0][xc + 2][xr] = a0.z; xs[0][xc + 3][xr] = a0.w;
        xs[0][xc + 4][xr] = a1.x; xs[0][xc + 5][xr] = a1.y;
        xs[0][xc + 6][xr] = a1.z; xs[0][xc + 7][xr] = a1.w;
        *(float4*)&ws[0][wr][wc]     = *(const float4*)&W[(size_t)(kbase + wr) * PW + bn + wc];
        *(float4*)&ws[0][wr][wc + 4] = *(const float4*)&W[(size_t)(kbase + wr) * PW + bn + wc + 4];
    }
    __syncthreads();

#pragma unroll
    for (int ch = 0; ch < 4; ch++) {
        const int cur = ch & 1;
        const int nxt = cur ^ 1;
        const int k1 = kbase + (ch + 1) * 32;

        float4 a0, a1, w0, w1;
        if (ch < 3) {
            a0 = *(const float4*)&x[(size_t)(bm + xr) * DD + k1 + xc];
            a1 = *(const float4*)&x[(size_t)(bm + xr) * DD + k1 + xc + 4];
            w0 = *(const float4*)&W[(size_t)(k1 + wr) * PW + bn + wc];
            w1 = *(const float4*)&W[(size_t)(k1 + wr) * PW + bn + wc + 4];
        }

        float4 av0 = *(const float4*)&xs[cur][0][ty * 4];
        float4 bv0 = *(const float4*)&ws[cur][0][tx * 4];
#pragma unroll
        for (int k = 0; k < 32; k++) {
            float4 av1, bv1;
            if (k < 31) {
                av1 = *(const float4*)&xs[cur][k + 1][ty * 4];
                bv1 = *(const float4*)&ws[cur][k + 1][tx * 4];
            }
            float a_[4] = {av0.x, av0.y, av0.z, av0.w};
            float b_[4] = {bv0.x, bv0.y, bv0.z, bv0.w};
#pragma unroll
            for (int i = 0; i < 4; i++)
#pragma unroll
                for (int j = 0; j < 4; j++)
                    acc[i][j] = fmaf(a_[i], b_[j], acc[i][j]);
            av0 = av1; bv0 = bv1;
        }

        if (ch < 3) {
            xs[nxt][xc + 0][xr] = a0.x; xs[nxt][xc + 1][xr] = a0.y;
            xs[nxt][xc + 2][xr] = a0.z; xs[nxt][xc + 3][xr] = a0.w;
            xs[nxt][xc + 4][xr] = a1.x; xs[nxt][xc + 5][xr] = a1.y;
            xs[nxt][xc + 6][xr] = a1.z; xs[nxt][xc + 7][xr] = a1.w;
            *(float4*)&ws[nxt][wr][wc]     = w0;
            *(float4*)&ws[nxt][wr][wc + 4] = w1;
            __syncthreads();
        }
    }

    float* dst = (blockIdx.z == 0) ? g_projA : g_projB;
#pragma unroll
    for (int i = 0; i < 4; i++) {
        float4 v = make_float4(acc[i][0], acc[i][1], acc[i][2], acc[i][3]);
        *(float4*)&dst[(size_t)(bm + ty * 4 + i) * PW + bn + tx * 4] = v;
    }
}

// ---------------------------------------------------------------------------
// Kernel 2 (fused): sums the two split-K partials on the fly.
// dt = softplus(dt_raw @ W_dt + b_dt); pack {dt, dt*x};
// out = x*delta; pack {beta, gamma} per n.
// ---------------------------------------------------------------------------
__global__ void dt_kernel(const float* __restrict__ x, const float* __restrict__ Wdt,
                          const float* __restrict__ bdt, const float* __restrict__ delta,
                          float* __restrict__ out) {
    int r = blockIdx.x;
    int t = threadIdx.x;
    __shared__ float sp[DT];
    if (t < DT) sp[t] = g_projA[r * PW + t] + g_projB[r * PW + t];
    __syncthreads();
    float acc = bdt[t];
#pragma unroll
    for (int k = 0; k < DT; k++)
        acc = fmaf(sp[k], Wdt[k * DD + t], acc);
    float dt = fmaxf(acc, 0.f) + log1pf(__expf(-fabsf(acc)));
    float xv = x[r * DD + t];
    int idx = r * DD + t;
    g_ddx[idx] = make_float2(dt, dt * xv);
    out[idx]   = xv * delta[t];
    float be = g_projA[r * PW + DT + t]      + g_projB[r * PW + DT + t];
    float ga = g_projA[r * PW + DT + DD + t] + g_projB[r * PW + DT + DD + t];
    g_bg2[(size_t)r * NN + t] = make_float2(be, ga);
}

// ---------------------------------------------------------------------------
// Kernel 3: sequential scan.  (R11/R12 proven version — float2 dd, 2 EX2/step.)
// ONE CTA per (b, d) (512 CTAs, 128 threads); each lane owns 2 n.
// dd preloaded to smem once per CTA; bg via one LDG.128 per lane per step.
// ---------------------------------------------------------------------------

#define LOAD_BATCH(BUF, LB) do {                                              \
    _Pragma("unroll")                                                         \
    for (int k_ = 0; k_ < 8; k_++) {                                          \
        bg[BUF][k_] = bgp[(size_t)((LB) + k_) * (NN / 2)];                    \
        dd[BUF][k_] = sdd[(LB) + k_];                                         \
    }                                                                         \
} while (0)

#define TREDUCE8(YL, VOUT) do {                                               \
    float s_, r0_, r1_, r2_, r3_, q0_, q1_;                                   \
    s_  = bt0 ? YL[0] : YL[1];                                                \
    r0_ = (bt0 ? YL[1] : YL[0]) + __shfl_xor_sync(fm, s_, 1);                 \
    s_  = bt0 ? YL[2] : YL[3];                                                \
    r1_ = (bt0 ? YL[3] : YL[2]) + __shfl_xor_sync(fm, s_, 1);                 \
    s_  = bt0 ? YL[4] : YL[5];                                                \
    r2_ = (bt0 ? YL[5] : YL[4]) + __shfl_xor_sync(fm, s_, 1);                 \
    s_  = bt0 ? YL[6] : YL[7];                                                \
    r3_ = (bt0 ? YL[7] : YL[6]) + __shfl_xor_sync(fm, s_, 1);                 \
    s_  = bt1 ? r0_ : r1_;                                                    \
    q0_ = (bt1 ? r1_ : r0_) + __shfl_xor_sync(fm, s_, 2);                     \
    s_  = bt1 ? r2_ : r3_;                                                    \
    q1_ = (bt1 ? r3_ : r2_) + __shfl_xor_sync(fm, s_, 2);                     \
    s_  = bt2 ? q0_ : q1_;                                                    \
    VOUT = (bt2 ? q1_ : q0_) + __shfl_xor_sync(fm, s_, 4);                    \
    VOUT += __shfl_xor_sync(fm, VOUT, 8);                                     \
    VOUT += __shfl_xor_sync(fm, VOUT, 16);                                    \
} while (0)

#define COMPUTE_BATCH(BUF, LB) do {                                           \
    float yl_[8];                                                             \
    _Pragma("unroll")                                                         \
    for (int k_ = 0; k_ < 8; k_++) {                                          \
        float dt_  = dd[BUF][k_].x;                                           \
        float dtx_ = dd[BUF][k_].y;                                           \
        float a0_ = ex2_approx(dt_ * a2v0);                                   \
        float a1_ = ex2_approx(dt_ * a2v1);                                   \
        st0 = fmaf(a0_, st0, dtx_ * bg[BUF][k_].x);                           \
        st1 = fmaf(a1_, st1, dtx_ * bg[BUF][k_].z);                           \
        yl_[k_] = fmaf(st0, bg[BUF][k_].y, st1 * bg[BUF][k_].w);              \
    }                                                                         \
    float v_;                                                                 \
    TREDUCE8(yl_, v_);                                                        \
    if (lane < 8) ypart[warp * LL + (LB) + lane] = v_;                        \
} while (0)

__global__ void __launch_bounds__(128, 4) scan_kernel(float* __restrict__ out,
                                                      const float* __restrict__ alog) {
    __shared__ float2 sdd[LL + 16];
    __shared__ float  ypart[4 * LL];

    const int warp = threadIdx.x >> 5;
    const int lane = threadIdx.x & 31;
    const int bd = blockIdx.x;
    const int b = bd >> 8;
    const int d = bd & 255;
    const int p = warp * 32 + lane;   // n-pair index: n = 2p, 2p+1

    for (int i = threadIdx.x; i < LL; i += 128)
        sdd[i] = g_ddx[(size_t)(b * LL + i) * DD + d];
    __syncthreads();

    const float L2E = 1.4426950408889634f;
    float a2v0 = -__expf(alog[d * NN + 2 * p])     * L2E;
    float a2v1 = -__expf(alog[d * NN + 2 * p + 1]) * L2E;
    float st0 = 0.f, st1 = 0.f;

    const float4* bgp = (const float4*)(g_bg2 + (size_t)(b * LL) * NN) + p;
    float* outp = out + (size_t)b * LL * DD + d;

    const unsigned fm = 0xffffffffu;
    const int bt0 = lane & 1;
    const int bt1 = (lane >> 1) & 1;
    const int bt2 = (lane >> 2) & 1;

    float4 bg[2][8];
    float2 dd[2][8];

    LOAD_BATCH(0, 0);

#pragma unroll 1
    for (int lb = 0; lb < LL; lb += 16) {
        LOAD_BATCH(1, lb + 8);
        COMPUTE_BATCH(0, lb);
        LOAD_BATCH(0, lb + 16);    // over-prefetch lands in padding (unused)
        COMPUTE_BATCH(1, lb + 8);
    }

    __syncthreads();

#pragma unroll
    for (int i = 0; i < 4; i++) {
        int l = threadIdx.x + i * 128;
        float y = ypart[l] + ypart[LL + l] + ypart[2 * LL + l] + ypart[3 * LL + l];
        outp[l * DD] += y;
    }
}

// ---------------------------------------------------------------------------
extern "C" void kernel_launch(void* const* d_in, const int* in_sizes, int n_in,
                              void* d_out, int out_size) {
    const float* x      = (const float*)d_in[0];  // [2,512,256]
    const float* W_in   = (const float*)d_in[1];  // [256,576]
    const float* W_dt   = (const float*)d_in[2];  // [64,256]
    const float* b_dt   = (const float*)d_in[3];  // [256]
    const float* alog   = (const float*)d_in[4];  // [256,256]
    const float* delta  = (const float*)d_in[5];  // [256]
    float* out = (float*)d_out;                   // [2,512,256]

    dim3 pgrid(PW / 64, (BB * LL) / 64, 2);       // (9, 16, 2) = 288 CTAs
    proj_kernel<<<pgrid, 256>>>(x, W_in);

    dt_kernel<<<BB * LL, 256>>>(x, W_dt, b_dt, delta, out);

    scan_kernel<<<BB * DD, 128>>>(out, alog);
}